// round 16
// baseline (speedup 1.0000x reference)
#include <cuda_runtime.h>

#define N_FWD  8192
#define T_LEN  4096
#define PAD    2048
#define B_MAX  64
#define FROW   4104           // g_F row stride in float2 (4097 rounded up)
#define FTH    512
#define ITH    256

// Complex padding (interleaved float2, radix-16 stride pattern)
#define P16(i)  ((i) + ((i) >> 4))
#define INV_CP  4352          // P16(4095)=4350 -> 4352 float2
#define FWD_CP  8704          // P16(8191)=8702 -> 8704 float2

#define LOG_OFF (-9.0109133472792881f)   // -ln(8192): folds 1/n into the log

__device__ float2 g_F[B_MAX * FROW];   // half spectra F[k], k in [0,4096]

// cwt twiddle tables, [r*256 + tid], coalesced per-lane. Filled in fwd kernel.
__device__ float2 g_T1 [4096];  // e^{+2 pi i (2 tid r)/8192}      (stage1 pass0)
__device__ float2 g_T1b[4096];  // e^{+2 pi i tid(2r+1)/8192}      (stage1 pass1, A folded)
__device__ float2 g_T2 [4096];  // e^{+2 pi i (tid&~15) r/4096}    (stage2)

__device__ __forceinline__ void cmulf(float& zr, float& zi,
                                      float ar, float ai, float br, float bi) {
    zr = ar * br - ai * bi;
    zi = ar * bi + ai * br;
}

// ===========================================================================
// Register-tree store16c (fwd kernel only): c_r = c0 * w1^r, depth<=4.
// ===========================================================================
__device__ __forceinline__ void store16c(float2* d,
                                         const float* yr, const float* yi,
                                         int o, int m,
                                         float c0r, float c0i,
                                         float w1r, float w1i)
{
    float w2r = w1r*w1r - w1i*w1i, w2i = 2.0f*w1r*w1i;
    float w4r = w2r*w2r - w2i*w2i, w4i = 2.0f*w2r*w2i;
    float w8r = w4r*w4r - w4i*w4i, w8i = 2.0f*w4r*w4i;

    float cr[16], ci[16];
    cr[0] = c0r; ci[0] = c0i;
    cmulf(cr[1], ci[1], cr[0], ci[0], w1r, w1i);
    cmulf(cr[2], ci[2], cr[0], ci[0], w2r, w2i);
    cmulf(cr[3], ci[3], cr[1], ci[1], w2r, w2i);
    #pragma unroll
    for (int r = 4; r < 8; ++r)  cmulf(cr[r], ci[r], cr[r-4], ci[r-4], w4r, w4i);
    #pragma unroll
    for (int r = 8; r < 16; ++r) cmulf(cr[r], ci[r], cr[r-8], ci[r-8], w8r, w8i);

    #pragma unroll
    for (int r = 0; r < 16; ++r)
        d[P16(o + r*m)] = make_float2(yr[r]*cr[r] - yi[r]*ci[r],
                                      yr[r]*ci[r] + yi[r]*cr[r]);
}

// Table-sourced store16c (cwt kernel): tw points at table + tid; row stride 256.
// 16 coalesced, L2-hot LDG.64, front-batched; no power-tree FMAs.
__device__ __forceinline__ void store16c_tbl(float2* d,
                                             const float* yr, const float* yi,
                                             int o, int m,
                                             const float2* __restrict__ tw)
{
    float2 c[16];
    #pragma unroll
    for (int r = 0; r < 16; ++r) c[r] = tw[r * 256];
    #pragma unroll
    for (int r = 0; r < 16; ++r)
        d[P16(o + r*m)] = make_float2(yr[r]*c[r].x - yi[r]*c[r].y,
                                      yr[r]*c[r].y + yi[r]*c[r].x);
}

// ===========================================================================
// 16-pt DFT butterflies (Cooley radix-4^2). INV: e^{+2pi i jr/16},
// FWD: e^{-2pi i jr/16}.
// ===========================================================================
#define CQ16 0.70710678118654752440f
#define C816 0.92387953251128675613f
#define S816 0.38268343236508977173f

__device__ __forceinline__ void bfly16_inv(const float* xr, const float* xi,
                                           float* yr, float* yi)
{
    float sr[16], si[16];
    #pragma unroll
    for (int b = 0; b < 4; ++b) {
        float p0r=xr[b],    p0i=xi[b];
        float p1r=xr[b+4],  p1i=xi[b+4];
        float p2r=xr[b+8],  p2i=xi[b+8];
        float p3r=xr[b+12], p3i=xi[b+12];
        float u0r=p0r+p2r, u0i=p0i+p2i;
        float u1r=p0r-p2r, u1i=p0i-p2i;
        float u2r=p1r+p3r, u2i=p1i+p3i;
        float u3r=p1r-p3r, u3i=p1i-p3i;
        sr[b]    = u0r+u2r; si[b]    = u0i+u2i;
        sr[b+4]  = u1r-u3i; si[b+4]  = u1i+u3r;
        sr[b+8]  = u0r-u2r; si[b+8]  = u0i-u2i;
        sr[b+12] = u1r+u3i; si[b+12] = u1i-u3r;
    }

    const float Tr[4][4] = {{1,1,1,1},
                            {1, C816,  CQ16,  S816},
                            {1, CQ16, 0.0f,  -CQ16},
                            {1, S816, -CQ16, -C816}};
    const float Ti[4][4] = {{0,0,0,0},
                            {0, S816,  CQ16,  C816},
                            {0, CQ16, 1.0f,   CQ16},
                            {0, C816,  CQ16, -S816}};

    #pragma unroll
    for (int r1 = 0; r1 < 4; ++r1) {
        float zr[4], zi[4];
        #pragma unroll
        for (int b = 0; b < 4; ++b)
            cmulf(zr[b], zi[b], sr[4*r1+b], si[4*r1+b], Tr[b][r1], Ti[b][r1]);
        float u0r=zr[0]+zr[2], u0i=zi[0]+zi[2];
        float u1r=zr[0]-zr[2], u1i=zi[0]-zi[2];
        float u2r=zr[1]+zr[3], u2i=zi[1]+zi[3];
        float u3r=zr[1]-zr[3], u3i=zi[1]-zi[3];
        yr[r1]    = u0r+u2r; yi[r1]    = u0i+u2i;
        yr[r1+4]  = u1r-u3i; yi[r1+4]  = u1i+u3r;
        yr[r1+8]  = u0r-u2r; yi[r1+8]  = u0i-u2i;
        yr[r1+12] = u1r+u3i; yi[r1+12] = u1i-u3r;
    }
}

__device__ __forceinline__ void bfly16_fwd(const float* xr, const float* xi,
                                           float* yr, float* yi)
{
    float sr[16], si[16];
    #pragma unroll
    for (int b = 0; b < 4; ++b) {
        float p0r=xr[b],    p0i=xi[b];
        float p1r=xr[b+4],  p1i=xi[b+4];
        float p2r=xr[b+8],  p2i=xi[b+8];
        float p3r=xr[b+12], p3i=xi[b+12];
        float u0r=p0r+p2r, u0i=p0i+p2i;
        float u1r=p0r-p2r, u1i=p0i-p2i;
        float u2r=p1r+p3r, u2i=p1i+p3i;
        float u3r=p1r-p3r, u3i=p1i-p3i;
        sr[b]    = u0r+u2r; si[b]    = u0i+u2i;
        sr[b+4]  = u1r+u3i; si[b+4]  = u1i-u3r;
        sr[b+8]  = u0r-u2r; si[b+8]  = u0i-u2i;
        sr[b+12] = u1r-u3i; si[b+12] = u1i+u3r;
    }

    const float Tr[4][4] = {{1,1,1,1},
                            {1, C816,  CQ16,  S816},
                            {1, CQ16, 0.0f,  -CQ16},
                            {1, S816, -CQ16, -C816}};
    const float Ti[4][4] = {{0,0,0,0},
                            {0, -S816, -CQ16, -C816},
                            {0, -CQ16, -1.0f, -CQ16},
                            {0, -C816, -CQ16,  S816}};

    #pragma unroll
    for (int r1 = 0; r1 < 4; ++r1) {
        float zr[4], zi[4];
        #pragma unroll
        for (int b = 0; b < 4; ++b)
            cmulf(zr[b], zi[b], sr[4*r1+b], si[4*r1+b], Tr[b][r1], Ti[b][r1]);
        float u0r=zr[0]+zr[2], u0i=zi[0]+zi[2];
        float u1r=zr[0]-zr[2], u1i=zi[0]-zi[2];
        float u2r=zr[1]+zr[3], u2i=zi[1]+zi[3];
        float u3r=zr[1]-zr[3], u3i=zi[1]-zi[3];
        yr[r1]    = u0r+u2r; yi[r1]    = u0i+u2i;
        yr[r1+4]  = u1r+u3i; yi[r1+4]  = u1i-u3r;
        yr[r1+8]  = u0r-u2r; yi[r1+8]  = u0i-u2i;
        yr[r1+12] = u1r-u3i; yi[r1+12] = u1i+u3r;
    }
}

// Partial inverse 16-pt DFT: compute only outputs r = 4..11 into y[r-4].
__device__ __forceinline__ void bfly16_inv_mid(const float* xr, const float* xi,
                                               float* yr, float* yi)
{
    float sr[16], si[16];
    #pragma unroll
    for (int b = 0; b < 4; ++b) {
        float p0r=xr[b],    p0i=xi[b];
        float p1r=xr[b+4],  p1i=xi[b+4];
        float p2r=xr[b+8],  p2i=xi[b+8];
        float p3r=xr[b+12], p3i=xi[b+12];
        float u0r=p0r+p2r, u0i=p0i+p2i;
        float u1r=p0r-p2r, u1i=p0i-p2i;
        float u2r=p1r+p3r, u2i=p1i+p3i;
        float u3r=p1r-p3r, u3i=p1i-p3i;
        sr[b]    = u0r+u2r; si[b]    = u0i+u2i;
        sr[b+4]  = u1r-u3i; si[b+4]  = u1i+u3r;
        sr[b+8]  = u0r-u2r; si[b+8]  = u0i-u2i;
        sr[b+12] = u1r+u3i; si[b+12] = u1i-u3r;
    }

    const float Tr[4][4] = {{1,1,1,1},
                            {1, C816,  CQ16,  S816},
                            {1, CQ16, 0.0f,  -CQ16},
                            {1, S816, -CQ16, -C816}};
    const float Ti[4][4] = {{0,0,0,0},
                            {0, S816,  CQ16,  C816},
                            {0, CQ16, 1.0f,   CQ16},
                            {0, C816,  CQ16, -S816}};

    #pragma unroll
    for (int r1 = 0; r1 < 4; ++r1) {
        float zr[4], zi[4];
        #pragma unroll
        for (int b = 0; b < 4; ++b)
            cmulf(zr[b], zi[b], sr[4*r1+b], si[4*r1+b], Tr[b][r1], Ti[b][r1]);
        float u0r=zr[0]+zr[2], u0i=zi[0]+zi[2];
        float u1r=zr[0]-zr[2], u1i=zi[0]-zi[2];
        float u2r=zr[1]+zr[3], u2i=zi[1]+zi[3];
        float u3r=zr[1]-zr[3], u3i=zi[1]-zi[3];
        yr[r1]     = u1r - u3i; yi[r1]     = u1i + u3r;
        yr[r1 + 4] = u0r - u2r; yi[r1 + 4] = u0i - u2i;
    }
}

extern __shared__ float sm_[];

// ===========================================================================
// FORWARD 8192-pt FFT: radix-16 x3 + final radix-2 fused with half-spectrum
// store. Also fills the cwt twiddle tables (zero extra launches).
// ===========================================================================
__global__ void __launch_bounds__(FTH, 1)
fwd_fft_kernel(const float* __restrict__ in)
{
    float2* A  = (float2*)sm_;
    float2* Bb = A + FWD_CP;

    const int b = blockIdx.x, tid = threadIdx.x;
    const float* x = in + b * T_LEN;

    // ---- cwt twiddle-table fill (4096 of the 32768 threads; ~free) ----
    {
        int gid = b * FTH + tid;
        if (gid < 4096) {
            int r = gid >> 8, t = gid & 255;
            float s, c;
            sincospif((float)(t * r) * (1.0f / 2048.0f), &s, &c);
            g_T1[gid] = make_float2(c, s);
            sincospif((float)(t * (2 * r + 1)) * (1.0f / 4096.0f), &s, &c);
            g_T1b[gid] = make_float2(c, s);
            sincospif((float)((t & ~15) * r) * (1.0f / 2048.0f), &s, &c);
            g_T2[gid] = make_float2(c, s);
        }
    }

    float xr[16], xi[16], yr[16], yi[16];

    // ---- stage 1 (m=1, jm=tid) fused with reflect-pad load
    #pragma unroll
    for (int q = 0; q < 16; ++q) {
        int i = tid + q * 512;
        int src;
        if (i < PAD)              src = PAD - 1 - i;
        else if (i < PAD + T_LEN) src = i - PAD;
        else                      src = (2 * T_LEN + PAD - 1) - i;
        xr[q] = x[src]; xi[q] = 0.0f;
    }
    bfly16_fwd(xr, xi, yr, yi);
    {
        float ss, cc;                       // w1 = e^{-2 pi i tid/8192}
        sincospif((float)tid * (1.0f / 4096.0f), &ss, &cc);
        store16c(A, yr, yi, 16 * tid, 1, 1.0f, 0.0f, cc, -ss);
    }
    __syncthreads();

    // ---- stage 2 (m=16)
    #pragma unroll
    for (int q = 0; q < 16; ++q) {
        float2 v = A[P16(tid + q * 512)];
        xr[q] = v.x; xi[q] = v.y;
    }
    bfly16_fwd(xr, xi, yr, yi);
    {
        int k = tid & 15, jm = tid - k;
        float ss, cc;                       // e^{-2 pi i jm/8192}
        sincospif((float)jm * (1.0f / 4096.0f), &ss, &cc);
        store16c(Bb, yr, yi, 16 * jm + k, 16, 1.0f, 0.0f, cc, -ss);
    }
    __syncthreads();

    // ---- stage 3 (m=256)
    #pragma unroll
    for (int q = 0; q < 16; ++q) {
        float2 v = Bb[P16(tid + q * 512)];
        xr[q] = v.x; xi[q] = v.y;
    }
    bfly16_fwd(xr, xi, yr, yi);
    {
        int k = tid & 255, jm = tid - k;
        float ss, cc;                       // e^{-2 pi i jm/8192}
        sincospif((float)jm * (1.0f / 4096.0f), &ss, &cc);
        store16c(A, yr, yi, 16 * jm + k, 256, 1.0f, 0.0f, cc, -ss);
    }
    __syncthreads();

    // ---- final radix-2 (m=4096, w=1): keep only k in [0,4096]
    float2* Fo = g_F + b * FROW;
    #pragma unroll
    for (int q = 0; q < 8; ++q) {
        int k = tid + q * 512;
        float2 u = A[P16(k)], v = A[P16(k + 4096)];
        Fo[k] = make_float2(u.x + v.x, u.y + v.y);
        if (k == 0) Fo[4096] = make_float2(u.x - v.x, u.y - v.y);
    }
}

// ===========================================================================
// CWT inverse kernel: radix-16 Stockham (R14/R15 structure). Delta: stage-1
// and stage-2 output twiddles come from coalesced L2-hot per-thread tables
// (g_T1/g_T1b/g_T2) instead of register power trees; sincospif prologue gone.
// ===========================================================================
__global__ void __launch_bounds__(ITH, 2)
cwt_kernel(const float* __restrict__ wft, float* __restrict__ out, int S)
{
    float2* A  = (float2*)sm_;
    float2* Bb = A + INV_CP;

    const int tid = threadIdx.x;
    const int s = blockIdx.x % S, b = blockIdx.x / S;
    const float2* __restrict__ F = g_F + b * FROW;
    const float*  __restrict__ w = wft + (size_t)s * N_FWD;

    float2 fn = F[4096];
    float  gn = w[4096];
    float  nyr = fn.x * gn, nyi = fn.y * gn;

    const int jm2 = tid & ~15;                      // stage-2 offset

    // B(q) = e^{+i pi q/16} constants for the pass-1 rotation
    const float BQr[16] = { 1.0f,  0.98078528f,  0.92387953f,  0.83146961f,
                            0.70710678f,  0.55557023f,  0.38268343f,  0.19509032f,
                            0.0f, -0.19509032f, -0.38268343f, -0.55557023f,
                           -0.70710678f, -0.83146961f, -0.92387953f, -0.98078528f };
    const float BQi[16] = { 0.0f,  0.19509032f,  0.38268343f,  0.55557023f,
                            0.70710678f,  0.83146961f,  0.92387953f,  0.98078528f,
                            1.0f,  0.98078528f,  0.92387953f,  0.83146961f,
                            0.70710678f,  0.55557023f,  0.38268343f,  0.19509032f };

    float ev[8];   // pass-0 log values (same thread & columns in pass 1)

    #pragma unroll
    for (int pass = 0; pass < 2; ++pass) {
        float xr[16], xi[16], yr[16], yi[16];

        // ---- stage 1 (m=1, jm=tid): fused global load + spectrum multiply.
        // Pass-1 rotation A(tid)*B(q): B(q) constants here, A folded into T1b.
        #pragma unroll
        for (int q = 0; q < 16; ++q) {
            int k = tid + q * 256;
            float2 f = F[k];
            float  g = w[k];
            float vr = f.x * g, vi = f.y * g;
            if (pass) {
                float br = BQr[q], bi = BQi[q];
                float r2 = vr * br - vi * bi;
                float i2 = vr * bi + vi * br;
                vr = r2; vi = i2;
            }
            xr[q] = vr; xi[q] = vi;
        }
        bfly16_inv(xr, xi, yr, yi);
        if (pass == 0) store16c_tbl(A, yr, yi, 16 * tid, 1, g_T1  + tid);
        else           store16c_tbl(A, yr, yi, 16 * tid, 1, g_T1b + tid);
        __syncthreads();

        // ---- stage 2 (m=16)
        #pragma unroll
        for (int q = 0; q < 16; ++q) {
            float2 v = A[P16(tid + q * 256)];
            xr[q] = v.x; xi[q] = v.y;
        }
        bfly16_inv(xr, xi, yr, yi);
        {
            int k2 = tid & 15;
            store16c_tbl(Bb, yr, yi, 16 * jm2 + k2, 16, g_T2 + tid);
        }
        __syncthreads();

        // ---- stage 3 (m=256, jm=0, W=1): partial butterfly (r=4..11 only)
        // fused with Nyquist + log|.| + output.
        #pragma unroll
        for (int q = 0; q < 16; ++q) {
            float2 v = Bb[P16(tid + q * 256)];
            xr[q] = v.x; xi[q] = v.y;
        }
        bfly16_inv_mid(xr, xi, yr, yi);   // yr/yi[0..7] == outputs r=4..11

        float nr = pass ? -nyr : nyr;
        float ni = pass ? -nyi : nyi;
        if (pass == 0) {
            #pragma unroll
            for (int j = 0; j < 8; ++j) {
                float a = yr[j] + nr, b2 = yi[j] + ni;
                ev[j] = fmaf(0.5f, __logf(a * a + b2 * b2), LOG_OFF);
            }
        } else {
            float2* o2 = (float2*)(out + (size_t)blockIdx.x * T_LEN);
            #pragma unroll
            for (int j = 0; j < 8; ++j) {
                float a = yr[j] + nr, b2 = yi[j] + ni;
                float lg = fmaf(0.5f, __logf(a * a + b2 * b2), LOG_OFF);
                o2[tid + 256 * j] = make_float2(ev[j], lg);
            }
        }
        // Barrier ordering for the next pass is provided by the barrier
        // after the next pass's stage-1 store.
    }
}

// ---------------------------------------------------------------------------
extern "C" void kernel_launch(void* const* d_in, const int* in_sizes, int n_in,
                              void* d_out, int out_size)
{
    const float* in  = (const float*)d_in[0];
    const float* wft = (const float*)d_in[1];
    float* out = (float*)d_out;

    const int B = in_sizes[0] / T_LEN;     // 64
    const int S = in_sizes[1] / N_FWD;     // 75

    const int fwd_smem = 2 * FWD_CP * sizeof(float2);      // 139264 B
    const int cwt_smem = 2 * INV_CP * sizeof(float2);      //  69632 B
    cudaFuncSetAttribute(fwd_fft_kernel,
                         cudaFuncAttributeMaxDynamicSharedMemorySize, fwd_smem);
    cudaFuncSetAttribute(cwt_kernel,
                         cudaFuncAttributeMaxDynamicSharedMemorySize, cwt_smem);

    fwd_fft_kernel<<<B, FTH, fwd_smem>>>(in);
    cwt_kernel<<<B * S, ITH, cwt_smem>>>(wft, out, S);
}

// round 17
// speedup vs baseline: 1.0624x; 1.0624x over previous
#include <cuda_runtime.h>

#define N_FWD  8192
#define T_LEN  4096
#define PAD    2048
#define B_MAX  64
#define FROW   4104           // g_F row stride in float2 (4097 rounded up)
#define FTH    512
#define ITH    256

// Complex padding (interleaved float2, radix-16 stride pattern)
#define P16(i)  ((i) + ((i) >> 4))
#define INV_CP  4352          // P16(4095)=4350 -> 4352 float2
#define FWD_CP  8704          // P16(8191)=8702 -> 8704 float2

#define LOG_OFF (-9.0109133472792881f)   // -ln(8192): folds 1/n into the log

__device__ float2 g_F[B_MAX * FROW];   // half spectra F[k], k in [0,4096]

__device__ __forceinline__ void cmulf(float& zr, float& zi,
                                      float ar, float ai, float br, float bi) {
    zr = ar * br - ai * bi;
    zi = ar * bi + ai * br;
}

// ===========================================================================
// store16c: c_r = c0 * w1^r via depth<=4 register tree (no memory twiddles).
// ===========================================================================
__device__ __forceinline__ void store16c(float2* d,
                                         const float* yr, const float* yi,
                                         int o, int m,
                                         float c0r, float c0i,
                                         float w1r, float w1i)
{
    float w2r = w1r*w1r - w1i*w1i, w2i = 2.0f*w1r*w1i;
    float w4r = w2r*w2r - w2i*w2i, w4i = 2.0f*w2r*w2i;
    float w8r = w4r*w4r - w4i*w4i, w8i = 2.0f*w4r*w4i;

    float cr[16], ci[16];
    cr[0] = c0r; ci[0] = c0i;
    cmulf(cr[1], ci[1], cr[0], ci[0], w1r, w1i);
    cmulf(cr[2], ci[2], cr[0], ci[0], w2r, w2i);
    cmulf(cr[3], ci[3], cr[1], ci[1], w2r, w2i);
    #pragma unroll
    for (int r = 4; r < 8; ++r)  cmulf(cr[r], ci[r], cr[r-4], ci[r-4], w4r, w4i);
    #pragma unroll
    for (int r = 8; r < 16; ++r) cmulf(cr[r], ci[r], cr[r-8], ci[r-8], w8r, w8i);

    #pragma unroll
    for (int r = 0; r < 16; ++r)
        d[P16(o + r*m)] = make_float2(yr[r]*cr[r] - yi[r]*ci[r],
                                      yr[r]*ci[r] + yi[r]*cr[r]);
}

// ===========================================================================
// 16-pt DFT butterflies (Cooley radix-4^2). INV: e^{+2pi i jr/16},
// FWD: e^{-2pi i jr/16}.
// ===========================================================================
#define CQ16 0.70710678118654752440f
#define C816 0.92387953251128675613f
#define S816 0.38268343236508977173f

__device__ __forceinline__ void bfly16_inv(const float* xr, const float* xi,
                                           float* yr, float* yi)
{
    float sr[16], si[16];
    #pragma unroll
    for (int b = 0; b < 4; ++b) {
        float p0r=xr[b],    p0i=xi[b];
        float p1r=xr[b+4],  p1i=xi[b+4];
        float p2r=xr[b+8],  p2i=xi[b+8];
        float p3r=xr[b+12], p3i=xi[b+12];
        float u0r=p0r+p2r, u0i=p0i+p2i;
        float u1r=p0r-p2r, u1i=p0i-p2i;
        float u2r=p1r+p3r, u2i=p1i+p3i;
        float u3r=p1r-p3r, u3i=p1i-p3i;
        sr[b]    = u0r+u2r; si[b]    = u0i+u2i;
        sr[b+4]  = u1r-u3i; si[b+4]  = u1i+u3r;
        sr[b+8]  = u0r-u2r; si[b+8]  = u0i-u2i;
        sr[b+12] = u1r+u3i; si[b+12] = u1i-u3r;
    }

    const float Tr[4][4] = {{1,1,1,1},
                            {1, C816,  CQ16,  S816},
                            {1, CQ16, 0.0f,  -CQ16},
                            {1, S816, -CQ16, -C816}};
    const float Ti[4][4] = {{0,0,0,0},
                            {0, S816,  CQ16,  C816},
                            {0, CQ16, 1.0f,   CQ16},
                            {0, C816,  CQ16, -S816}};

    #pragma unroll
    for (int r1 = 0; r1 < 4; ++r1) {
        float zr[4], zi[4];
        #pragma unroll
        for (int b = 0; b < 4; ++b)
            cmulf(zr[b], zi[b], sr[4*r1+b], si[4*r1+b], Tr[b][r1], Ti[b][r1]);
        float u0r=zr[0]+zr[2], u0i=zi[0]+zi[2];
        float u1r=zr[0]-zr[2], u1i=zi[0]-zi[2];
        float u2r=zr[1]+zr[3], u2i=zi[1]+zi[3];
        float u3r=zr[1]-zr[3], u3i=zi[1]-zi[3];
        yr[r1]    = u0r+u2r; yi[r1]    = u0i+u2i;
        yr[r1+4]  = u1r-u3i; yi[r1+4]  = u1i+u3r;
        yr[r1+8]  = u0r-u2r; yi[r1+8]  = u0i-u2i;
        yr[r1+12] = u1r+u3i; yi[r1+12] = u1i-u3r;
    }
}

__device__ __forceinline__ void bfly16_fwd(const float* xr, const float* xi,
                                           float* yr, float* yi)
{
    float sr[16], si[16];
    #pragma unroll
    for (int b = 0; b < 4; ++b) {
        float p0r=xr[b],    p0i=xi[b];
        float p1r=xr[b+4],  p1i=xi[b+4];
        float p2r=xr[b+8],  p2i=xi[b+8];
        float p3r=xr[b+12], p3i=xi[b+12];
        float u0r=p0r+p2r, u0i=p0i+p2i;
        float u1r=p0r-p2r, u1i=p0i-p2i;
        float u2r=p1r+p3r, u2i=p1i+p3i;
        float u3r=p1r-p3r, u3i=p1i-p3i;
        sr[b]    = u0r+u2r; si[b]    = u0i+u2i;
        sr[b+4]  = u1r+u3i; si[b+4]  = u1i-u3r;
        sr[b+8]  = u0r-u2r; si[b+8]  = u0i-u2i;
        sr[b+12] = u1r-u3i; si[b+12] = u1i+u3r;
    }

    const float Tr[4][4] = {{1,1,1,1},
                            {1, C816,  CQ16,  S816},
                            {1, CQ16, 0.0f,  -CQ16},
                            {1, S816, -CQ16, -C816}};
    const float Ti[4][4] = {{0,0,0,0},
                            {0, -S816, -CQ16, -C816},
                            {0, -CQ16, -1.0f, -CQ16},
                            {0, -C816, -CQ16,  S816}};

    #pragma unroll
    for (int r1 = 0; r1 < 4; ++r1) {
        float zr[4], zi[4];
        #pragma unroll
        for (int b = 0; b < 4; ++b)
            cmulf(zr[b], zi[b], sr[4*r1+b], si[4*r1+b], Tr[b][r1], Ti[b][r1]);
        float u0r=zr[0]+zr[2], u0i=zi[0]+zi[2];
        float u1r=zr[0]-zr[2], u1i=zi[0]-zi[2];
        float u2r=zr[1]+zr[3], u2i=zi[1]+zi[3];
        float u3r=zr[1]-zr[3], u3i=zi[1]-zi[3];
        yr[r1]    = u0r+u2r; yi[r1]    = u0i+u2i;
        yr[r1+4]  = u1r+u3i; yi[r1+4]  = u1i-u3r;
        yr[r1+8]  = u0r-u2r; yi[r1+8]  = u0i-u2i;
        yr[r1+12] = u1r-u3i; yi[r1+12] = u1i+u3r;
    }
}

// Partial inverse 16-pt DFT: compute only outputs r = 4..11 into y[r-4].
__device__ __forceinline__ void bfly16_inv_mid(const float* xr, const float* xi,
                                               float* yr, float* yi)
{
    float sr[16], si[16];
    #pragma unroll
    for (int b = 0; b < 4; ++b) {
        float p0r=xr[b],    p0i=xi[b];
        float p1r=xr[b+4],  p1i=xi[b+4];
        float p2r=xr[b+8],  p2i=xi[b+8];
        float p3r=xr[b+12], p3i=xi[b+12];
        float u0r=p0r+p2r, u0i=p0i+p2i;
        float u1r=p0r-p2r, u1i=p0i-p2i;
        float u2r=p1r+p3r, u2i=p1i+p3i;
        float u3r=p1r-p3r, u3i=p1i-p3i;
        sr[b]    = u0r+u2r; si[b]    = u0i+u2i;
        sr[b+4]  = u1r-u3i; si[b+4]  = u1i+u3r;
        sr[b+8]  = u0r-u2r; si[b+8]  = u0i-u2i;
        sr[b+12] = u1r+u3i; si[b+12] = u1i-u3r;
    }

    const float Tr[4][4] = {{1,1,1,1},
                            {1, C816,  CQ16,  S816},
                            {1, CQ16, 0.0f,  -CQ16},
                            {1, S816, -CQ16, -C816}};
    const float Ti[4][4] = {{0,0,0,0},
                            {0, S816,  CQ16,  C816},
                            {0, CQ16, 1.0f,   CQ16},
                            {0, C816,  CQ16, -S816}};

    #pragma unroll
    for (int r1 = 0; r1 < 4; ++r1) {
        float zr[4], zi[4];
        #pragma unroll
        for (int b = 0; b < 4; ++b)
            cmulf(zr[b], zi[b], sr[4*r1+b], si[4*r1+b], Tr[b][r1], Ti[b][r1]);
        float u0r=zr[0]+zr[2], u0i=zi[0]+zi[2];
        float u1r=zr[0]-zr[2], u1i=zi[0]-zi[2];
        float u2r=zr[1]+zr[3], u2i=zi[1]+zi[3];
        float u3r=zr[1]-zr[3], u3i=zi[1]-zi[3];
        yr[r1]     = u1r - u3i; yi[r1]     = u1i + u3r;
        yr[r1 + 4] = u0r - u2r; yi[r1 + 4] = u0i - u2i;
    }
}

extern __shared__ float sm_[];

// ===========================================================================
// FORWARD 8192-pt FFT: radix-16 x3 + final radix-2 fused with half-spectrum
// store (R15, unchanged).
// ===========================================================================
__global__ void __launch_bounds__(FTH, 1)
fwd_fft_kernel(const float* __restrict__ in)
{
    float2* A  = (float2*)sm_;
    float2* Bb = A + FWD_CP;

    const int b = blockIdx.x, tid = threadIdx.x;
    const float* x = in + b * T_LEN;

    float xr[16], xi[16], yr[16], yi[16];

    // ---- stage 1 (m=1, jm=tid) fused with reflect-pad load
    #pragma unroll
    for (int q = 0; q < 16; ++q) {
        int i = tid + q * 512;
        int src;
        if (i < PAD)              src = PAD - 1 - i;
        else if (i < PAD + T_LEN) src = i - PAD;
        else                      src = (2 * T_LEN + PAD - 1) - i;
        xr[q] = x[src]; xi[q] = 0.0f;
    }
    bfly16_fwd(xr, xi, yr, yi);
    {
        float ss, cc;                       // w1 = e^{-2 pi i tid/8192}
        sincospif((float)tid * (1.0f / 4096.0f), &ss, &cc);
        store16c(A, yr, yi, 16 * tid, 1, 1.0f, 0.0f, cc, -ss);
    }
    __syncthreads();

    // ---- stage 2 (m=16)
    #pragma unroll
    for (int q = 0; q < 16; ++q) {
        float2 v = A[P16(tid + q * 512)];
        xr[q] = v.x; xi[q] = v.y;
    }
    bfly16_fwd(xr, xi, yr, yi);
    {
        int k = tid & 15, jm = tid - k;
        float ss, cc;                       // e^{-2 pi i jm/8192}
        sincospif((float)jm * (1.0f / 4096.0f), &ss, &cc);
        store16c(Bb, yr, yi, 16 * jm + k, 16, 1.0f, 0.0f, cc, -ss);
    }
    __syncthreads();

    // ---- stage 3 (m=256)
    #pragma unroll
    for (int q = 0; q < 16; ++q) {
        float2 v = Bb[P16(tid + q * 512)];
        xr[q] = v.x; xi[q] = v.y;
    }
    bfly16_fwd(xr, xi, yr, yi);
    {
        int k = tid & 255, jm = tid - k;
        float ss, cc;                       // e^{-2 pi i jm/8192}
        sincospif((float)jm * (1.0f / 4096.0f), &ss, &cc);
        store16c(A, yr, yi, 16 * jm + k, 256, 1.0f, 0.0f, cc, -ss);
    }
    __syncthreads();

    // ---- final radix-2 (m=4096, w=1): keep only k in [0,4096]
    float2* Fo = g_F + b * FROW;
    #pragma unroll
    for (int q = 0; q < 8; ++q) {
        int k = tid + q * 512;
        float2 u = A[P16(k)], v = A[P16(k + 4096)];
        Fo[k] = make_float2(u.x + v.x, u.y + v.y);
        if (k == 0) Fo[4096] = make_float2(u.x - v.x, u.y - v.y);
    }
}

// ===========================================================================
// CWT inverse kernel: radix-16 Stockham (R15 structure). Single delta:
// G = F*wft is computed ONCE in pass 0 and held in registers (gr/gi[16]);
// pass 1 consumes it with the constant B(q) rotation — removes 16 LDG.64 +
// 16 LDG.32 + 32 FMUL per thread from pass 1.
// ===========================================================================
__global__ void __launch_bounds__(ITH, 2)
cwt_kernel(const float* __restrict__ wft, float* __restrict__ out, int S)
{
    float2* A  = (float2*)sm_;
    float2* Bb = A + INV_CP;

    const int tid = threadIdx.x;
    const int s = blockIdx.x % S, b = blockIdx.x / S;
    const float2* __restrict__ F = g_F + b * FROW;
    const float*  __restrict__ w = wft + (size_t)s * N_FWD;

    float2 fn = F[4096];
    float  gn = w[4096];
    float  nyr = fn.x * gn, nyi = fn.y * gn;

    // Hoisted, pass-invariant twiddle bases (2 sincospif per thread total).
    float sA, cA;                                   // A = e^{+2 pi i tid/8192}
    sincospif((float)tid * (1.0f / 4096.0f), &sA, &cA);
    float w1r = cA * cA - sA * sA;                  // stage-1 base = A^2
    float w1i = 2.0f * cA * sA;
    const int jm2 = tid & ~15;                      // stage-2 jm
    float s2s, s2c;                                 // e^{+2 pi i jm2/4096}
    sincospif((float)jm2 * (1.0f / 2048.0f), &s2s, &s2c);

    // B(q) = e^{+i pi q/16} constants for the pass-1 rotation
    const float BQr[16] = { 1.0f,  0.98078528f,  0.92387953f,  0.83146961f,
                            0.70710678f,  0.55557023f,  0.38268343f,  0.19509032f,
                            0.0f, -0.19509032f, -0.38268343f, -0.55557023f,
                           -0.70710678f, -0.83146961f, -0.92387953f, -0.98078528f };
    const float BQi[16] = { 0.0f,  0.19509032f,  0.38268343f,  0.55557023f,
                            0.70710678f,  0.83146961f,  0.92387953f,  0.98078528f,
                            1.0f,  0.98078528f,  0.92387953f,  0.83146961f,
                            0.70710678f,  0.55557023f,  0.38268343f,  0.19509032f };

    float ev[8];       // pass-0 log values (same thread & columns in pass 1)
    float gr[16], gi[16];   // G = F*wft, loaded once, reused in pass 1

    // ---- G load + multiply (once) ----
    #pragma unroll
    for (int q = 0; q < 16; ++q) {
        int k = tid + q * 256;
        float2 f = F[k];
        float  g = w[k];
        gr[q] = f.x * g;
        gi[q] = f.y * g;
    }

    #pragma unroll
    for (int pass = 0; pass < 2; ++pass) {
        float xr[16], xi[16], yr[16], yi[16];

        // ---- stage 1 (m=1, jm=tid): G (registers) + pass-1 B(q) rotation.
        if (pass == 0) {
            #pragma unroll
            for (int q = 0; q < 16; ++q) { xr[q] = gr[q]; xi[q] = gi[q]; }
        } else {
            #pragma unroll
            for (int q = 0; q < 16; ++q) {
                float br = BQr[q], bi = BQi[q];
                xr[q] = gr[q] * br - gi[q] * bi;
                xi[q] = gr[q] * bi + gi[q] * br;
            }
        }
        bfly16_inv(xr, xi, yr, yi);
        if (pass == 0) store16c(A, yr, yi, 16 * tid, 1, 1.0f, 0.0f, w1r, w1i);
        else           store16c(A, yr, yi, 16 * tid, 1, cA,   sA,   w1r, w1i);
        __syncthreads();

        // ---- stage 2 (m=16)
        #pragma unroll
        for (int q = 0; q < 16; ++q) {
            float2 v = A[P16(tid + q * 256)];
            xr[q] = v.x; xi[q] = v.y;
        }
        bfly16_inv(xr, xi, yr, yi);
        {
            int k2 = tid & 15;
            store16c(Bb, yr, yi, 16 * jm2 + k2, 16, 1.0f, 0.0f, s2c, s2s);
        }
        __syncthreads();

        // ---- stage 3 (m=256, jm=0, W=1): partial butterfly (r=4..11 only)
        // fused with Nyquist + log|.| + output.
        #pragma unroll
        for (int q = 0; q < 16; ++q) {
            float2 v = Bb[P16(tid + q * 256)];
            xr[q] = v.x; xi[q] = v.y;
        }
        bfly16_inv_mid(xr, xi, yr, yi);   // yr/yi[0..7] == outputs r=4..11

        float nr = pass ? -nyr : nyr;
        float ni = pass ? -nyi : nyi;
        if (pass == 0) {
            #pragma unroll
            for (int j = 0; j < 8; ++j) {
                float a = yr[j] + nr, b2 = yi[j] + ni;
                ev[j] = fmaf(0.5f, __logf(a * a + b2 * b2), LOG_OFF);
            }
        } else {
            float2* o2 = (float2*)(out + (size_t)blockIdx.x * T_LEN);
            #pragma unroll
            for (int j = 0; j < 8; ++j) {
                float a = yr[j] + nr, b2 = yi[j] + ni;
                float lg = fmaf(0.5f, __logf(a * a + b2 * b2), LOG_OFF);
                o2[tid + 256 * j] = make_float2(ev[j], lg);
            }
        }
        // Barrier ordering for the next pass is provided by the barrier
        // after the next pass's stage-1 store.
    }
}

// ---------------------------------------------------------------------------
extern "C" void kernel_launch(void* const* d_in, const int* in_sizes, int n_in,
                              void* d_out, int out_size)
{
    const float* in  = (const float*)d_in[0];
    const float* wft = (const float*)d_in[1];
    float* out = (float*)d_out;

    const int B = in_sizes[0] / T_LEN;     // 64
    const int S = in_sizes[1] / N_FWD;     // 75

    const int fwd_smem = 2 * FWD_CP * sizeof(float2);      // 139264 B
    const int cwt_smem = 2 * INV_CP * sizeof(float2);      //  69632 B
    cudaFuncSetAttribute(fwd_fft_kernel,
                         cudaFuncAttributeMaxDynamicSharedMemorySize, fwd_smem);
    cudaFuncSetAttribute(cwt_kernel,
                         cudaFuncAttributeMaxDynamicSharedMemorySize, cwt_smem);

    fwd_fft_kernel<<<B, FTH, fwd_smem>>>(in);
    cwt_kernel<<<B * S, ITH, cwt_smem>>>(wft, out, S);
}